// round 9
// baseline (speedup 1.0000x reference)
#include <cuda_runtime.h>
#include <math.h>

// ---------------------------------------------------------------------------
// DE3 fused: 256-bin histogram entropy, single kernel.
//   out = B * (8 + sum_i p_i log2 p_i),  p_i = counts[i] / (2048*2048)
//
// R4-R8 finding: the kernel is MLP-bound; register-buffer prefetch caps at
// ~8 LDG in flight (ptxas window) -> ~5 TB/s. This round gets MLP WITHOUT
// registers: cp.async (LDGSTS) staging into smem, per-thread private
// 3-slot ring (128 B/slot), commit_group/wait_group pipelining.
// Each thread consumes exactly the bytes it copied -> NO barriers in loop.
// In-flight: 2 slots x 128 B x 256 thr/SM = 64 KB/SM, register-independent.
//
// Histograms: per-thread u16, conflict-free (bank == lane), R8 layout:
//   counter(warp, lane, bin) at byte
//     warp*16384 + (bin>>1)*128 + lane*4 + (bin&1)*2
// 296 blocks x 128 thr (2/SM). smem/block = 64K histo + 48K staging = 112K.
// Max ~1792 elems/thread < 65535 (u16 safe; packed reduce carry-free).
// ---------------------------------------------------------------------------

#define NUM_BINS 256
#define THREADS  128
#define BLOCKS   296
#define HISTO_BYTES 65536
#define NBUF     3
#define SLOT_F4  8                    // 8 float4 = 128 B per thread per slot
#define CHUNK_F4 (THREADS * SLOT_F4)  // 1024 float4 = 16 KB per block-chunk
#define STAGE_BYTES (NBUF * CHUNK_F4 * 16)     // 49152
#define SMEM_BYTES  (HISTO_BYTES + STAGE_BYTES) // 114688

__device__ unsigned int g_counts[NUM_BINS];   // zero-init at load
__device__ unsigned int g_done;

__device__ __forceinline__ void cp_async16(unsigned smem_addr, const void* gptr) {
    asm volatile("cp.async.cg.shared.global [%0], [%1], 16;\n"
                 :: "r"(smem_addr), "l"(gptr));
}
__device__ __forceinline__ void cp_commit() {
    asm volatile("cp.async.commit_group;\n" ::: "memory");
}
__device__ __forceinline__ void cp_wait2() {
    asm volatile("cp.async.wait_group 2;\n" ::: "memory");
}

__global__ void __launch_bounds__(THREADS)
de3_fused(const float4* __restrict__ in4, int n4,
          const float* __restrict__ in, int n,
          float* __restrict__ out)
{
    extern __shared__ unsigned char smem[];
    unsigned smem_u32;
    asm("{ .reg .u64 t; cvta.to.shared.u64 t, %1; cvt.u32.u64 %0, t; }"
        : "=r"(smem_u32) : "l"(smem));

    const unsigned t    = threadIdx.x;
    const unsigned lane = t & 31u;
    const unsigned warp = t >> 5;
    const unsigned lanebase = (warp << 14) + (lane << 2);  // warp*16KB + lane*4

    const int nchunks = n4 / CHUNK_F4;
    const unsigned stage_u32 = smem_u32 + HISTO_BYTES;
    // thread t's 8 slots within a chunk buffer: float4 indices t + k*128
    // slot s base (this thread): stage + s*16384 + t*16 ... strided by 128*16

    // ---- prologue: issue NBUF chunks' copies first (start DRAM early) -----
    int issue_c = blockIdx.x;
    #pragma unroll
    for (int s = 0; s < NBUF; ++s) {
        if (issue_c < nchunks) {
            const float4* src = in4 + issue_c * CHUNK_F4 + t;
            unsigned dst = stage_u32 + (unsigned)s * (CHUNK_F4 * 16) + t * 16u;
            #pragma unroll
            for (int k = 0; k < SLOT_F4; ++k)
                cp_async16(dst + (unsigned)k * (THREADS * 16), src + k * THREADS);
        }
        cp_commit();
        issue_c += gridDim.x;
    }

    // ---- zero private histograms (overlaps with in-flight copies) ---------
    {
        uint4* z = reinterpret_cast<uint4*>(smem);
        #pragma unroll
        for (int i = t; i < HISTO_BYTES / 16; i += THREADS)
            z[i] = make_uint4(0u, 0u, 0u, 0u);
    }
    __syncthreads();

    // conflict-free u16 bump: bank == lane always
    #define DE3_BUMP(V) do {                                                  \
        unsigned b_ = __float2uint_rz(fminf((V), 255.0f));                    \
        unsigned h_ = b_ & 1u;                                                \
        unsigned short* c_ = reinterpret_cast<unsigned short*>(               \
            smem + (b_ * 64u + lanebase - h_ * 62u));                         \
        *c_ = (unsigned short)(*c_ + 1u);                                     \
    } while (0)
    #define DE3_BUMP4(Q) do { DE3_BUMP((Q).x); DE3_BUMP((Q).y);              \
                              DE3_BUMP((Q).z); DE3_BUMP((Q).w); } while (0)

    // ---- main loop: no block barriers; per-thread cp.async pipeline -------
    int proc_c = blockIdx.x;
    int buf = 0;
    const float4* stage_f4 = reinterpret_cast<const float4*>(smem + HISTO_BYTES);
    while (proc_c < nchunks) {
        cp_wait2();                     // oldest group (this buf) complete
        const float4* slot = stage_f4 + buf * CHUNK_F4 + t;
        #pragma unroll
        for (int k = 0; k < SLOT_F4; ++k) {
            float4 v = slot[k * THREADS];
            DE3_BUMP4(v);
        }
        // refill this buf with the next chunk (only this thread's bytes)
        if (issue_c < nchunks) {
            const float4* src = in4 + issue_c * CHUNK_F4 + t;
            unsigned dst = stage_u32 + (unsigned)buf * (CHUNK_F4 * 16) + t * 16u;
            #pragma unroll
            for (int k = 0; k < SLOT_F4; ++k)
                cp_async16(dst + (unsigned)k * (THREADS * 16), src + k * THREADS);
        }
        cp_commit();                    // always commit: keeps group count fixed
        issue_c += gridDim.x;
        proc_c  += gridDim.x;
        buf = (buf + 1) % NBUF;
    }

    // ---- tails: float4s beyond nchunks*CHUNK_F4, then n%4 scalars ---------
    for (int i = nchunks * CHUNK_F4 + blockIdx.x * THREADS + (int)t;
         i < n4; i += gridDim.x * THREADS) {
        float4 v = __ldcs(in4 + i);
        DE3_BUMP4(v);
    }
    if (blockIdx.x == 0 && (int)t < (n & 3)) {
        float v = in[(n & ~3) + (int)t];
        DE3_BUMP(v);
    }
    #undef DE3_BUMP4
    #undef DE3_BUMP
    __syncthreads();

    // ---- block reduction (R8, proven) -------------------------------------
    // Word (warp w, row r, lane l) at word-index w*4096 + r*32 + l holds
    // thread (w,l)'s u16 counters for bins (2r, 2r+1).
    const unsigned j = t;
    unsigned tot0 = 0u, tot1 = 0u;   // bins 2j, 2j+1
    {
        const unsigned* w32 = reinterpret_cast<const unsigned*>(smem);
        #pragma unroll
        for (unsigned w = 0; w < 4; ++w) {
            const unsigned rowbase = w * 4096u + j * 32u;
            unsigned acc = 0u;
            #pragma unroll
            for (unsigned k = 0; k < 32; ++k) {
                unsigned l = (k + j) & 31u;
                acc += w32[rowbase + l];
            }
            tot0 += acc & 0xFFFFu;
            tot1 += acc >> 16;
        }
    }
    atomicAdd(&g_counts[2u * j],      tot0);
    atomicAdd(&g_counts[2u * j + 1u], tot1);

    // ---- last-block finalize ----------------------------------------------
    __threadfence();
    __shared__ unsigned ticket;
    if (t == 0) ticket = atomicAdd(&g_done, 1u);
    __syncthreads();

    if (ticket == gridDim.x - 1) {
        const float inv_temp = 1.0f / 4194304.0f;   // 1/(2048*2048)
        unsigned c0 = __ldcg(&g_counts[j]);
        unsigned c1 = __ldcg(&g_counts[j + 128]);
        double term = 0.0;
        if (c0) { float p = (float)c0 * inv_temp; term += (double)(p * log2f(p)); }
        if (c1) { float p = (float)c1 * inv_temp; term += (double)(p * log2f(p)); }

        #pragma unroll
        for (int o = 16; o > 0; o >>= 1)
            term += __shfl_down_sync(0xffffffffu, term, o);

        __shared__ double sred[4];
        if ((j & 31u) == 0u) sred[j >> 5] = term;
        __syncthreads();
        if (j == 0) {
            double s = sred[0] + sred[1] + sred[2] + sred[3];
            float B = (float)(n >> 22);              // n / (2048*2048)
            out[0] = (float)((double)B * (8.0 + s));
        }
        __syncthreads();
        // reset device globals for the next graph replay
        g_counts[j] = 0u;
        g_counts[j + 128] = 0u;
        if (j == 0) g_done = 0u;
    }
}

extern "C" void kernel_launch(void* const* d_in, const int* in_sizes, int n_in,
                              void* d_out, int out_size) {
    const float* img = (const float*)d_in[0];
    int n = in_sizes[0];
    cudaFuncSetAttribute(de3_fused,
                         cudaFuncAttributeMaxDynamicSharedMemorySize, SMEM_BYTES);
    de3_fused<<<BLOCKS, THREADS, SMEM_BYTES>>>(
        (const float4*)img, n >> 2, img, n, (float*)d_out);
}